// round 13
// baseline (speedup 1.0000x reference)
#include <cuda_runtime.h>
#include <cuda_fp16.h>
#include <cstdint>

#define EXPERTS 16
#define SEQ     2048
#define DIM     1024
#define HID     4096

// Tiled+swizzled fp16 scratch. A-tile = 128x64 (16KB), B-tile = 64x128 (16KB),
// stored exactly in the smem image so the mainloop does contiguous 16KB bulk copies.
__device__ __half g_xT [(size_t)EXPERTS * SEQ * DIM];   // x   A-tiles [e][mt][kt]
__device__ __half g_w1T[(size_t)EXPERTS * DIM * HID];   // w1  B-tiles [e][kt][nt]
__device__ __half g_w2T[(size_t)EXPERTS * HID * DIM];   // w2  B-tiles [e][kt][nt]
__device__ __half g_hT [(size_t)EXPERTS * SEQ * HID];   // gelu(x@w1) A-tiles [e][mt][kt]

// ---------------- PTX helpers (base sm_103-safe) ----------------
static __device__ __forceinline__ uint32_t smem_u32(const void* p) {
    return (uint32_t)__cvta_generic_to_shared(p);
}
static __device__ __forceinline__ void mbar_init(uint32_t a, uint32_t cnt) {
    asm volatile("mbarrier.init.shared.b64 [%0], %1;" :: "r"(a), "r"(cnt) : "memory");
}
static __device__ __forceinline__ void mbar_expect(uint32_t a, uint32_t bytes) {
    asm volatile("mbarrier.arrive.expect_tx.shared.b64 _, [%0], %1;"
                 :: "r"(a), "r"(bytes) : "memory");
}
static __device__ __forceinline__ void mbar_arrive(uint32_t a) {
    asm volatile("mbarrier.arrive.shared.b64 _, [%0];" :: "r"(a) : "memory");
}
static __device__ __forceinline__ void bulk_g2s(uint32_t dst, const void* src,
                                                uint32_t bytes, uint32_t mbar) {
    asm volatile(
        "cp.async.bulk.shared::cluster.global.mbarrier::complete_tx::bytes "
        "[%0], [%1], %2, [%3];"
        :: "r"(dst), "l"(src), "r"(bytes), "r"(mbar) : "memory");
}
static __device__ __forceinline__ void mbar_wait(uint32_t a, uint32_t parity) {
    asm volatile(
        "{\n\t.reg .pred P;\n\t"
        "WL%=:\n\t"
        "mbarrier.try_wait.parity.acquire.cta.shared::cta.b64 P, [%0], %1, 0x989680;\n\t"
        "@!P bra WL%=;\n\t}"
        :: "r"(a), "r"(parity) : "memory");
}
static __device__ __forceinline__ void ldsm_x4(uint32_t* r, uint32_t a) {
    asm volatile("ldmatrix.sync.aligned.m8n8.x4.shared.b16 {%0,%1,%2,%3}, [%4];"
                 : "=r"(r[0]), "=r"(r[1]), "=r"(r[2]), "=r"(r[3]) : "r"(a));
}
static __device__ __forceinline__ void ldsm_x4_t(uint32_t* r, uint32_t a) {
    asm volatile("ldmatrix.sync.aligned.m8n8.x4.trans.shared.b16 {%0,%1,%2,%3}, [%4];"
                 : "=r"(r[0]), "=r"(r[1]), "=r"(r[2]), "=r"(r[3]) : "r"(a));
}
static __device__ __forceinline__ void mma16816(float* d, const uint32_t* a,
                                                uint32_t b0, uint32_t b1) {
    asm volatile(
        "mma.sync.aligned.m16n8k16.row.col.f32.f16.f16.f32 "
        "{%0,%1,%2,%3}, {%4,%5,%6,%7}, {%8,%9}, {%0,%1,%2,%3};"
        : "+f"(d[0]), "+f"(d[1]), "+f"(d[2]), "+f"(d[3])
        : "r"(a[0]), "r"(a[1]), "r"(a[2]), "r"(a[3]), "r"(b0), "r"(b1));
}
static __device__ __forceinline__ float gelu_f(float v) {
    return 0.5f * v * (1.0f + erff(v * 0.70710678118654752f));
}

// w-convert helper: one float4 of w[e][k][nd] -> B-tile layout [e][kt][nt][64x128 sw]
static __device__ __forceinline__ void cvt_w_one(const float4* __restrict__ in,
                                                 __half* __restrict__ out,
                                                 int Kd, int Nd, size_t i) {
    size_t base = i * 4;
    int n = (int)(base % Nd);
    size_t kn = base / Nd;
    int k = (int)(kn % Kd);
    int e = (int)(kn / Kd);
    float4 v = in[i];
    __half2 a = __floats2half2_rn(v.x, v.y);
    __half2 b = __floats2half2_rn(v.z, v.w);
    int kt = k >> 6, r = k & 63, nt = n >> 7, c = n & 127;
    size_t tile = ((size_t)(e * (Kd >> 6) + kt) * (Nd >> 7) + nt) << 14;
    char* p = (char*)out + tile + (size_t)r * 256 + ((c >> 6) << 7)
            + (((((c >> 3) & 7) ^ (r & 7)) << 4) + (c & 7) * 2);
    uint2 o;
    o.x = *reinterpret_cast<uint32_t*>(&a);
    o.y = *reinterpret_cast<uint32_t*>(&b);
    *reinterpret_cast<uint2*>(p) = o;
}

// -------- GEMM: C[128x128]; 4 warps (2x2), warp tile 64x64; 2 CTAs/SM --------
// Linear grid: blocks [0,NTILES) do GEMM; blocks >= NTILES do w-convert (if any).
constexpr int STAGES = 3, NTHR = 128;
constexpr int TILE_B = 16384;
constexpr int ST_B   = 2 * TILE_B;
constexpr int OFF_T  = 1024;
constexpr int SMEM_TOTAL = OFF_T + STAGES * ST_B;    // 99328 -> 2 CTA/SM
constexpr int CVB = 4096;                            // cvt tail blocks (GEMM1)
// ctrl: full[s] at sb+8*s (count 1), empty[s] at sb+64+8*s (count 4 warps)

template <int GELU_OUT>
__global__ void __launch_bounds__(NTHR, 2)
gemm_bulk(const __half* __restrict__ Atiles, const __half* __restrict__ Btiles,
          void* __restrict__ C0, int KT, int lgTX, int NT, int NTILES,
          int ldc, size_t sC,
          const float4* __restrict__ cvt_in, __half* __restrict__ cvt_out,
          int cvt_Kd, int cvt_Nd, size_t cvt_n4)
{
    const int tid = threadIdx.x;
    const int bid = blockIdx.x;

    if (bid >= NTILES) {                     // ---- cvt role (tail blocks) ----
        size_t idx = (size_t)(bid - NTILES) * NTHR + tid;
        size_t stride = (size_t)(gridDim.x - NTILES) * NTHR;
        for (size_t i = idx; i < cvt_n4; i += stride)
            cvt_w_one(cvt_in, cvt_out, cvt_Kd, cvt_Nd, i);
        return;
    }

    extern __shared__ char smem[];
    const uint32_t sb = smem_u32(smem);
    const int bx = bid & ((1 << lgTX) - 1);
    const int by = (bid >> lgTX) & 15;
    const int e  = bid >> (lgTX + 4);

    const char* Abase = (const char*)Atiles + ((size_t)(e * 16 + by) * KT) * TILE_B;
    const char* Bbase = (const char*)Btiles + ((size_t)e * KT * NT + bx) * TILE_B;
    const size_t bstep = (size_t)NT * TILE_B;

    if (tid == 0) {
#pragma unroll
        for (int s = 0; s < STAGES; s++) {
            mbar_init(sb + 8 * s, 1);        // full
            mbar_init(sb + 64 + 8 * s, 4);   // empty: one arrive per warp
        }
    }
    __syncthreads();                         // barrier-init visibility (only sync)

    const int wid = tid >> 5, lid = tid & 31;
    const int wm = wid & 1, wn = wid >> 1;   // 2(M) x 2(N), warp tile 64x64
    const int sub = lid >> 3, rr = lid & 7;
    const int rowA0 = wm * 64 + rr + ((sub & 1) << 3);   // + mt*16
    const int krow0 = rr + ((sub & 1) << 3);             // + kk*16
    const int nch0  = wn * 8 + (sub >> 1);               // + nt2*2

    float acc[4][8][4];
#pragma unroll
    for (int mt = 0; mt < 4; mt++)
#pragma unroll
        for (int nt = 0; nt < 8; nt++)
#pragma unroll
            for (int q = 0; q < 4; q++) acc[mt][nt][q] = 0.f;

    // producer prologue: fill slots 0..STAGES-2
    if (tid == 0) {
#pragma unroll
        for (int it = 0; it < STAGES - 1; it++) {
            uint32_t mb = sb + 8 * it, da = sb + OFF_T + it * ST_B;
            mbar_expect(mb, ST_B);
            bulk_g2s(da,          Abase + (size_t)it * TILE_B, TILE_B, mb);
            bulk_g2s(da + TILE_B, Bbase + (size_t)it * bstep,  TILE_B, mb);
        }
    }

    for (int i = 0; i < KT; i++) {
        const int s = i % STAGES;
        mbar_wait(sb + 8 * s, (i / STAGES) & 1);
        // producer refills slot for iteration nx = i+STAGES-1
        if (tid == 0) {
            int nx = i + STAGES - 1;
            if (nx < KT) {
                int s2 = nx % STAGES;
                if (nx >= STAGES)            // wait all warps released old contents
                    mbar_wait(sb + 64 + 8 * s2, ((nx - STAGES) / STAGES) & 1);
                uint32_t mb = sb + 8 * s2, da = sb + OFF_T + s2 * ST_B;
                mbar_expect(mb, ST_B);
                bulk_g2s(da,          Abase + (size_t)nx * TILE_B, TILE_B, mb);
                bulk_g2s(da + TILE_B, Bbase + (size_t)nx * bstep,  TILE_B, mb);
            }
        }

        const uint32_t sa  = sb + OFF_T + s * ST_B;
        const uint32_t sbb = sa + TILE_B;
#pragma unroll
        for (int kk = 0; kk < 4; kk++) {
            uint32_t bf[4][4];
#pragma unroll
            for (int nt2 = 0; nt2 < 4; nt2++) {
                int krow = kk * 16 + krow0;
                int cw = nch0 + nt2 * 2;
                ldsm_x4_t(bf[nt2], sbb + krow * 256 + ((cw >> 3) << 7) +
                                   (((cw & 7) ^ (krow & 7)) << 4));
            }
#pragma unroll
            for (int mt = 0; mt < 4; mt++) {
                uint32_t af[4];
                int row = rowA0 + mt * 16;
                int ch = 2 * kk + (sub >> 1);
                ldsm_x4(af, sa + row * 128 + ((ch ^ (row & 7)) << 4));
#pragma unroll
                for (int nt2 = 0; nt2 < 4; nt2++) {
                    mma16816(acc[mt][nt2 * 2],     af, bf[nt2][0], bf[nt2][1]);
                    mma16816(acc[mt][nt2 * 2 + 1], af, bf[nt2][2], bf[nt2][3]);
                }
            }
        }
        // EARLY RELEASE: all LDSM reads of slot s are retired (MMAs consumed them)
        if (lid == 0) mbar_arrive(sb + 64 + 8 * s);
    }

    // Epilogue. C frag m16n8: lane -> rows r0, r0+8 ; cols cq, cq+1.
    const int r0 = lid >> 2, cq = (lid & 3) * 2;
    if (GELU_OUT) {
        // write g_hT as GEMM2 A-tiles: tile (e, mt=by, ktg = bx*2 + (cl>>6))
        char* Hb = (char*)C0 + ((size_t)(e * (SEQ / 128) + by) * (HID / 64) + bx * 2) * TILE_B;
#pragma unroll
        for (int mt = 0; mt < 4; mt++) {
            int r1 = wm * 64 + mt * 16 + r0;          // r1&7 == r0&7
#pragma unroll
            for (int nt = 0; nt < 8; nt++) {
                int cl = wn * 64 + nt * 8 + cq;
                int cc = cl & 63;
                float* q = acc[mt][nt];
                __half2 h0 = __floats2half2_rn(gelu_f(q[0]), gelu_f(q[1]));
                __half2 h1 = __floats2half2_rn(gelu_f(q[2]), gelu_f(q[3]));
                char* p = Hb + ((size_t)(cl >> 6) << 14)
                             + ((((cc >> 3) ^ (r0 & 7)) << 4) + (cc & 7) * 2);
                *reinterpret_cast<__half2*>(p + (size_t)r1 * 128) = h0;
                *reinterpret_cast<__half2*>(p + (size_t)(r1 + 8) * 128) = h1;
            }
        }
    } else {
        const int m0 = by * 128, n0 = bx * 128;
#pragma unroll
        for (int mt = 0; mt < 4; mt++) {
            int rbase = m0 + wm * 64 + mt * 16 + r0;
#pragma unroll
            for (int nt = 0; nt < 8; nt++) {
                int col = n0 + wn * 64 + nt * 8 + cq;
                float* q = acc[mt][nt];
                float* C = (float*)C0 + e * sC + (size_t)rbase * ldc + col;
                *reinterpret_cast<float2*>(C) = make_float2(q[0], q[1]);
                *reinterpret_cast<float2*>(C + (size_t)8 * ldc) = make_float2(q[2], q[3]);
            }
        }
    }
}

// ---------------- conversion: fp32 -> fp16 tiled+swizzled ----------------
// x [e][n][d] -> A-tiles [e][mt][kt][128x64 swizzled]
__global__ void cvt_x_tiled(const float4* __restrict__ in) {
    size_t i = (size_t)blockIdx.x * blockDim.x + threadIdx.x;  // E*SEQ*DIM/4
    size_t base = i * 4;
    int d = (int)(base % DIM);
    size_t nd = base / DIM;
    int n = (int)(nd % SEQ);
    int e = (int)(nd / SEQ);
    float4 v = in[i];
    __half2 a = __floats2half2_rn(v.x, v.y);
    __half2 b = __floats2half2_rn(v.z, v.w);
    int mt = n >> 7, r = n & 127, kt = d >> 6, c = d & 63;
    size_t tile = ((size_t)(e * (SEQ / 128) + mt) * (DIM / 64) + kt) << 14;
    char* p = (char*)g_xT + tile + (size_t)r * 128
            + ((((c >> 3) ^ (r & 7)) << 4) + (c & 7) * 2);
    uint2 o;
    o.x = *reinterpret_cast<uint32_t*>(&a);
    o.y = *reinterpret_cast<uint32_t*>(&b);
    *reinterpret_cast<uint2*>(p) = o;
}

// standalone w-convert (used for w1, which GEMM1 depends on)
__global__ void cvt_w_tiled(const float4* __restrict__ in, __half* __restrict__ out,
                            int Kd, int Nd) {
    size_t i = (size_t)blockIdx.x * blockDim.x + threadIdx.x;
    cvt_w_one(in, out, Kd, Nd, i);
}

// ---------------- launch ----------------
extern "C" void kernel_launch(void* const* d_in, const int* in_sizes, int n_in,
                              void* d_out, int out_size) {
    const float* x  = (const float*)d_in[0];
    const float* w1 = (const float*)d_in[1];
    const float* w2 = (const float*)d_in[2];
    float* out = (float*)d_out;

    __half *pxT, *pw1T, *pw2T, *phT;
    cudaGetSymbolAddress((void**)&pxT,  g_xT);
    cudaGetSymbolAddress((void**)&pw1T, g_w1T);
    cudaGetSymbolAddress((void**)&pw2T, g_w2T);
    cudaGetSymbolAddress((void**)&phT,  g_hT);

    cudaFuncSetAttribute(gemm_bulk<1>, cudaFuncAttributeMaxDynamicSharedMemorySize, SMEM_TOTAL);
    cudaFuncSetAttribute(gemm_bulk<0>, cudaFuncAttributeMaxDynamicSharedMemorySize, SMEM_TOTAL);

    const size_t nx = (size_t)EXPERTS * SEQ * DIM;   // 33.5M
    const size_t nw = (size_t)EXPERTS * DIM * HID;   // 67.1M
    cvt_x_tiled<<<(unsigned)(nx / 4 / 256), 256>>>((const float4*)x);
    cvt_w_tiled<<<(unsigned)(nw / 4 / 256), 256>>>((const float4*)w1, pw1T, DIM, HID);
    // (w2 conversion is fused into GEMM1's tail blocks below)

    // GEMM1: hT = gelu(x @ w1); tiles 8192 (bx 0..31 | by 0..15 | e 0..15)
    //        + CVB tail blocks converting w2 under GEMM1's idle DRAM.
    gemm_bulk<1><<<8192 + CVB, NTHR, SMEM_TOTAL>>>(
        pxT, pw1T, phT, DIM / 64, 5, HID / 128, 8192, 0, 0,
        (const float4*)w2, pw2T, HID, DIM, nw / 4);

    // GEMM2: out = hid @ w2; tiles 2048 (bx 0..7 | by 0..15 | e 0..15)
    gemm_bulk<0><<<2048, NTHR, SMEM_TOTAL>>>(
        phT, pw2T, out, HID / 64, 3, DIM / 128, 2048, DIM, (size_t)SEQ * DIM,
        nullptr, nullptr, 0, 0, 0);
}

// round 15
// speedup vs baseline: 1.1671x; 1.1671x over previous
#include <cuda_runtime.h>
#include <cuda_fp16.h>
#include <cstdint>

#define EXPERTS 16
#define SEQ     2048
#define DIM     1024
#define HID     4096

// Tiled+swizzled fp16 scratch. A-tile = 128x64 (16KB), B-tile = 64x128 (16KB),
// stored exactly in the smem image so the mainloop does contiguous 16KB bulk copies.
__device__ __half g_xT [(size_t)EXPERTS * SEQ * DIM];   // x   A-tiles [e][mt][kt]
__device__ __half g_w1T[(size_t)EXPERTS * DIM * HID];   // w1  B-tiles [e][kt][nt]
__device__ __half g_w2T[(size_t)EXPERTS * HID * DIM];   // w2  B-tiles [e][kt][nt]
__device__ __half g_hT [(size_t)EXPERTS * SEQ * HID];   // gelu(x@w1) A-tiles [e][mt][kt]

// ---------------- PTX helpers (base sm_103-safe) ----------------
static __device__ __forceinline__ uint32_t smem_u32(const void* p) {
    return (uint32_t)__cvta_generic_to_shared(p);
}
static __device__ __forceinline__ void mbar_init(uint32_t a, uint32_t cnt) {
    asm volatile("mbarrier.init.shared.b64 [%0], %1;" :: "r"(a), "r"(cnt) : "memory");
}
static __device__ __forceinline__ void mbar_expect(uint32_t a, uint32_t bytes) {
    asm volatile("mbarrier.arrive.expect_tx.shared.b64 _, [%0], %1;"
                 :: "r"(a), "r"(bytes) : "memory");
}
static __device__ __forceinline__ void mbar_arrive(uint32_t a) {
    asm volatile("mbarrier.arrive.shared.b64 _, [%0];" :: "r"(a) : "memory");
}
static __device__ __forceinline__ void bulk_g2s(uint32_t dst, const void* src,
                                                uint32_t bytes, uint32_t mbar) {
    asm volatile(
        "cp.async.bulk.shared::cluster.global.mbarrier::complete_tx::bytes "
        "[%0], [%1], %2, [%3];"
        :: "r"(dst), "l"(src), "r"(bytes), "r"(mbar) : "memory");
}
static __device__ __forceinline__ void mbar_wait(uint32_t a, uint32_t parity) {
    asm volatile(
        "{\n\t.reg .pred P;\n\t"
        "WL%=:\n\t"
        "mbarrier.try_wait.parity.acquire.cta.shared::cta.b64 P, [%0], %1, 0x989680;\n\t"
        "@!P bra WL%=;\n\t}"
        :: "r"(a), "r"(parity) : "memory");
}
static __device__ __forceinline__ void ldsm_x4(uint32_t* r, uint32_t a) {
    asm volatile("ldmatrix.sync.aligned.m8n8.x4.shared.b16 {%0,%1,%2,%3}, [%4];"
                 : "=r"(r[0]), "=r"(r[1]), "=r"(r[2]), "=r"(r[3]) : "r"(a));
}
static __device__ __forceinline__ void ldsm_x4_t(uint32_t* r, uint32_t a) {
    asm volatile("ldmatrix.sync.aligned.m8n8.x4.trans.shared.b16 {%0,%1,%2,%3}, [%4];"
                 : "=r"(r[0]), "=r"(r[1]), "=r"(r[2]), "=r"(r[3]) : "r"(a));
}
static __device__ __forceinline__ void mma16816(float* d, const uint32_t* a,
                                                uint32_t b0, uint32_t b1) {
    asm volatile(
        "mma.sync.aligned.m16n8k16.row.col.f32.f16.f16.f32 "
        "{%0,%1,%2,%3}, {%4,%5,%6,%7}, {%8,%9}, {%0,%1,%2,%3};"
        : "+f"(d[0]), "+f"(d[1]), "+f"(d[2]), "+f"(d[3])
        : "r"(a[0]), "r"(a[1]), "r"(a[2]), "r"(a[3]), "r"(b0), "r"(b1));
}
static __device__ __forceinline__ float gelu_f(float v) {
    return 0.5f * v * (1.0f + erff(v * 0.70710678118654752f));
}

// -------- GEMM: C[128x128]; 4 warps (2x2), warp tile 64x64; 2 CTAs/SM --------
constexpr int STAGES = 3, NTHR = 128;
constexpr int TILE_B = 16384;
constexpr int ST_B   = 2 * TILE_B;
constexpr int OFF_T  = 1024;
constexpr int SMEM_TOTAL = OFF_T + STAGES * ST_B;    // 99328 -> 2 CTA/SM
// ctrl: full[s] at sb+8*s (count 1), empty[s] at sb+64+8*s (count 4 warps)

template <int GELU_OUT>
__global__ void __launch_bounds__(NTHR, 2)
gemm_bulk(const __half* __restrict__ Atiles, const __half* __restrict__ Btiles,
          void* __restrict__ C0, int KT, int lgTX, int NT,
          int ldc, size_t sC)
{
    extern __shared__ char smem[];
    const uint32_t sb = smem_u32(smem);
    const int tid = threadIdx.x;
    const int bid = blockIdx.x;
    const int bx = bid & ((1 << lgTX) - 1);
    const int by = (bid >> lgTX) & 15;
    const int e  = bid >> (lgTX + 4);

    const char* Abase = (const char*)Atiles + ((size_t)(e * 16 + by) * KT) * TILE_B;
    const char* Bbase = (const char*)Btiles + ((size_t)e * KT * NT + bx) * TILE_B;
    const size_t bstep = (size_t)NT * TILE_B;

    if (tid == 0) {
#pragma unroll
        for (int s = 0; s < STAGES; s++) {
            mbar_init(sb + 8 * s, 1);        // full
            mbar_init(sb + 64 + 8 * s, 4);   // empty: one arrive per warp
        }
    }
    __syncthreads();                         // barrier-init visibility (only sync)

    const int wid = tid >> 5, lid = tid & 31;
    const int wm = wid & 1, wn = wid >> 1;   // 2(M) x 2(N), warp tile 64x64
    const int sub = lid >> 3, rr = lid & 7;
    const int rowA0 = wm * 64 + rr + ((sub & 1) << 3);   // + mt*16
    const int krow0 = rr + ((sub & 1) << 3);             // + kk*16
    const int nch0  = wn * 8 + (sub >> 1);               // + nt2*2

    float acc[4][8][4];
#pragma unroll
    for (int mt = 0; mt < 4; mt++)
#pragma unroll
        for (int nt = 0; nt < 8; nt++)
#pragma unroll
            for (int q = 0; q < 4; q++) acc[mt][nt][q] = 0.f;

    // producer prologue: fill slots 0..STAGES-2
    if (tid == 0) {
#pragma unroll
        for (int it = 0; it < STAGES - 1; it++) {
            uint32_t mb = sb + 8 * it, da = sb + OFF_T + it * ST_B;
            mbar_expect(mb, ST_B);
            bulk_g2s(da,          Abase + (size_t)it * TILE_B, TILE_B, mb);
            bulk_g2s(da + TILE_B, Bbase + (size_t)it * bstep,  TILE_B, mb);
        }
    }

    for (int i = 0; i < KT; i++) {
        const int s = i % STAGES;
        mbar_wait(sb + 8 * s, (i / STAGES) & 1);
        // producer refills slot for iteration nx = i+STAGES-1
        if (tid == 0) {
            int nx = i + STAGES - 1;
            if (nx < KT) {
                int s2 = nx % STAGES;
                if (nx >= STAGES)            // wait all warps released old contents
                    mbar_wait(sb + 64 + 8 * s2, ((nx - STAGES) / STAGES) & 1);
                uint32_t mb = sb + 8 * s2, da = sb + OFF_T + s2 * ST_B;
                mbar_expect(mb, ST_B);
                bulk_g2s(da,          Abase + (size_t)nx * TILE_B, TILE_B, mb);
                bulk_g2s(da + TILE_B, Bbase + (size_t)nx * bstep,  TILE_B, mb);
            }
        }

        const uint32_t sa  = sb + OFF_T + s * ST_B;
        const uint32_t sbb = sa + TILE_B;
#pragma unroll
        for (int kk = 0; kk < 4; kk++) {
            uint32_t bf[4][4];
#pragma unroll
            for (int nt2 = 0; nt2 < 4; nt2++) {
                int krow = kk * 16 + krow0;
                int cw = nch0 + nt2 * 2;
                ldsm_x4_t(bf[nt2], sbb + krow * 256 + ((cw >> 3) << 7) +
                                   (((cw & 7) ^ (krow & 7)) << 4));
            }
#pragma unroll
            for (int mt = 0; mt < 4; mt++) {
                uint32_t af[4];
                int row = rowA0 + mt * 16;
                int ch = 2 * kk + (sub >> 1);
                ldsm_x4(af, sa + row * 128 + ((ch ^ (row & 7)) << 4));
#pragma unroll
                for (int nt2 = 0; nt2 < 4; nt2++) {
                    mma16816(acc[mt][nt2 * 2],     af, bf[nt2][0], bf[nt2][1]);
                    mma16816(acc[mt][nt2 * 2 + 1], af, bf[nt2][2], bf[nt2][3]);
                }
            }
        }
        // EARLY RELEASE: all LDSM reads of slot s retired (MMAs consumed them)
        if (lid == 0) mbar_arrive(sb + 64 + 8 * s);
    }

    // Epilogue. C frag m16n8: lane -> rows r0, r0+8 ; cols cq, cq+1.
    const int r0 = lid >> 2, cq = (lid & 3) * 2;
    if (GELU_OUT) {
        // write g_hT as GEMM2 A-tiles: tile (e, mt=by, ktg = bx*2 + (cl>>6))
        char* Hb = (char*)C0 + ((size_t)(e * (SEQ / 128) + by) * (HID / 64) + bx * 2) * TILE_B;
#pragma unroll
        for (int mt = 0; mt < 4; mt++) {
            int r1 = wm * 64 + mt * 16 + r0;          // r1&7 == r0&7
#pragma unroll
            for (int nt = 0; nt < 8; nt++) {
                int cl = wn * 64 + nt * 8 + cq;
                int cc = cl & 63;
                float* q = acc[mt][nt];
                __half2 h0 = __floats2half2_rn(gelu_f(q[0]), gelu_f(q[1]));
                __half2 h1 = __floats2half2_rn(gelu_f(q[2]), gelu_f(q[3]));
                char* p = Hb + ((size_t)(cl >> 6) << 14)
                             + ((((cc >> 3) ^ (r0 & 7)) << 4) + (cc & 7) * 2);
                *reinterpret_cast<__half2*>(p + (size_t)r1 * 128) = h0;
                *reinterpret_cast<__half2*>(p + (size_t)(r1 + 8) * 128) = h1;
            }
        }
    } else {
        const int m0 = by * 128, n0 = bx * 128;
#pragma unroll
        for (int mt = 0; mt < 4; mt++) {
            int rbase = m0 + wm * 64 + mt * 16 + r0;
#pragma unroll
            for (int nt = 0; nt < 8; nt++) {
                int col = n0 + wn * 64 + nt * 8 + cq;
                float* q = acc[mt][nt];
                float* C = (float*)C0 + e * sC + (size_t)rbase * ldc + col;
                *reinterpret_cast<float2*>(C) = make_float2(q[0], q[1]);
                *reinterpret_cast<float2*>(C + (size_t)8 * ldc) = make_float2(q[2], q[3]);
            }
        }
    }
}

// ---------------- conversion: fp32 -> fp16 tiled+swizzled ----------------
// x [e][n][d] -> A-tiles [e][mt][kt][128x64 swizzled]
__global__ void cvt_x_tiled(const float4* __restrict__ in) {
    size_t i = (size_t)blockIdx.x * blockDim.x + threadIdx.x;  // E*SEQ*DIM/4
    size_t base = i * 4;
    int d = (int)(base % DIM);
    size_t nd = base / DIM;
    int n = (int)(nd % SEQ);
    int e = (int)(nd / SEQ);
    float4 v = in[i];
    __half2 a = __floats2half2_rn(v.x, v.y);
    __half2 b = __floats2half2_rn(v.z, v.w);
    int mt = n >> 7, r = n & 127, kt = d >> 6, c = d & 63;
    size_t tile = ((size_t)(e * (SEQ / 128) + mt) * (DIM / 64) + kt) << 14;
    char* p = (char*)g_xT + tile + (size_t)r * 128
            + ((((c >> 3) ^ (r & 7)) << 4) + (c & 7) * 2);
    uint2 o;
    o.x = *reinterpret_cast<uint32_t*>(&a);
    o.y = *reinterpret_cast<uint32_t*>(&b);
    *reinterpret_cast<uint2*>(p) = o;
}

// w [e][k][nd] -> B-tiles [e][kt][nt][64x128 swizzled]
__global__ void cvt_w_tiled(const float4* __restrict__ in, __half* __restrict__ out,
                            int Kd, int Nd) {
    size_t i = (size_t)blockIdx.x * blockDim.x + threadIdx.x;  // E*Kd*Nd/4
    size_t base = i * 4;
    int n = (int)(base % Nd);
    size_t kn = base / Nd;
    int k = (int)(kn % Kd);
    int e = (int)(kn / Kd);
    float4 v = in[i];
    __half2 a = __floats2half2_rn(v.x, v.y);
    __half2 b = __floats2half2_rn(v.z, v.w);
    int kt = k >> 6, r = k & 63, nt = n >> 7, c = n & 127;
    size_t tile = ((size_t)(e * (Kd >> 6) + kt) * (Nd >> 7) + nt) << 14;
    char* p = (char*)out + tile + (size_t)r * 256 + ((c >> 6) << 7)
            + (((((c >> 3) & 7) ^ (r & 7)) << 4) + (c & 7) * 2);
    uint2 o;
    o.x = *reinterpret_cast<uint32_t*>(&a);
    o.y = *reinterpret_cast<uint32_t*>(&b);
    *reinterpret_cast<uint2*>(p) = o;
}

// ---------------- launch ----------------
extern "C" void kernel_launch(void* const* d_in, const int* in_sizes, int n_in,
                              void* d_out, int out_size) {
    const float* x  = (const float*)d_in[0];
    const float* w1 = (const float*)d_in[1];
    const float* w2 = (const float*)d_in[2];
    float* out = (float*)d_out;

    __half *pxT, *pw1T, *pw2T, *phT;
    cudaGetSymbolAddress((void**)&pxT,  g_xT);
    cudaGetSymbolAddress((void**)&pw1T, g_w1T);
    cudaGetSymbolAddress((void**)&pw2T, g_w2T);
    cudaGetSymbolAddress((void**)&phT,  g_hT);

    cudaFuncSetAttribute(gemm_bulk<1>, cudaFuncAttributeMaxDynamicSharedMemorySize, SMEM_TOTAL);
    cudaFuncSetAttribute(gemm_bulk<0>, cudaFuncAttributeMaxDynamicSharedMemorySize, SMEM_TOTAL);

    const size_t nx = (size_t)EXPERTS * SEQ * DIM;   // 33.5M
    const size_t nw = (size_t)EXPERTS * DIM * HID;   // 67.1M
    cvt_x_tiled<<<(unsigned)(nx / 4 / 256), 256>>>((const float4*)x);
    cvt_w_tiled<<<(unsigned)(nw / 4 / 256), 256>>>((const float4*)w1, pw1T, DIM, HID);
    cvt_w_tiled<<<(unsigned)(nw / 4 / 256), 256>>>((const float4*)w2, pw2T, HID, DIM);

    // GEMM1: hT = gelu(x @ w1); tiles 8192 (bx 0..31 | by 0..15 | e 0..15)
    gemm_bulk<1><<<8192, NTHR, SMEM_TOTAL>>>(
        pxT, pw1T, phT, DIM / 64, 5, HID / 128, 0, 0);

    // GEMM2: out = hid @ w2; tiles 2048 (bx 0..7 | by 0..15 | e 0..15)
    gemm_bulk<0><<<2048, NTHR, SMEM_TOTAL>>>(
        phT, pw2T, out, HID / 64, 3, DIM / 128, DIM, (size_t)SEQ * DIM);
}